// round 3
// baseline (speedup 1.0000x reference)
#include <cuda_runtime.h>

#define EMB 64
#define NSEG 4096
#define MAIN_GRID 888          // 148 SMs x 6 CTAs -> exactly one wave at occ>=6
#define THREADS 256

__device__ float g_wvo[EMB];   // w_value @ w_out
__device__ float g_c;          // b_value.w_out + b_out
__device__ float g_b0;         // b_out[0]
__device__ float g_se[NSEG];   // sum exp(score) per segment
__device__ float g_sev[NSEG];  // sum exp(score)*v per segment

// PRE: zero accumulators (16 blocks cover 4096), block 0 also computes wvo/c.
__global__ __launch_bounds__(THREADS)
void pre_kernel(const float* __restrict__ w_value,
                const float* __restrict__ b_value,
                const float* __restrict__ w_out,
                const float* __restrict__ b_out) {
    int i = blockIdx.x * blockDim.x + threadIdx.x;
    if (i < NSEG) { g_se[i] = 0.f; g_sev[i] = 0.f; }
    if (blockIdx.x == 0 && threadIdx.x < EMB) {
        int e = threadIdx.x;
        float s = 0.f;
#pragma unroll
        for (int h = 0; h < EMB; ++h) s = fmaf(__ldg(w_value + e * EMB + h), __ldg(w_out + h), s);
        g_wvo[e] = s;
        if (e == 0) {
            float c = 0.f;
            for (int h = 0; h < EMB; ++h) c = fmaf(__ldg(b_value + h), __ldg(w_out + h), c);
            g_c  = c + __ldg(b_out);
            g_b0 = __ldg(b_out);
        }
    }
}

// MAIN: flat streaming over all rows; leaders accumulate per-segment runs and
// flush to global atomics on segment change (ids sorted -> ~2-3 flushes/leader).
__global__ __launch_bounds__(THREADS)
void main_kernel(const float* __restrict__ emb,
                 const int*   __restrict__ ids,
                 const float* __restrict__ w_attn,
                 int Btot) {
    const int tid   = threadIdx.x;
    const int chunk = (Btot + MAIN_GRID - 1) / MAIN_GRID;
    const int start = blockIdx.x * chunk;
    const int end   = min(start + chunk, Btot);

    const int grp = tid & 15;           // column slice [4*grp, 4*grp+4)
    const int rl  = tid >> 4;           // row slot 0..15
    const float4 wa = reinterpret_cast<const float4*>(w_attn)[grp];
    const float4 wv = reinterpret_cast<const float4*>(g_wvo)[grp];

    int   curSeg = -1;
    float aSe = 0.f, aSev = 0.f;

    for (int base = start; base < end; base += 64) {
#pragma unroll
        for (int u = 0; u < 4; ++u) {
            const int row = base + u * 16 + rl;
            const bool valid = row < end;
            float4 e = make_float4(0.f, 0.f, 0.f, 0.f);
            if (valid) e = reinterpret_cast<const float4*>(emb + (size_t)row * EMB)[grp];

            float sp = e.x * wa.x + e.y * wa.y + e.z * wa.z + e.w * wa.w;
            float vp = e.x * wv.x + e.y * wv.y + e.z * wv.z + e.w * wv.w;
#pragma unroll
            for (int o = 8; o; o >>= 1) {
                sp += __shfl_xor_sync(0xffffffffu, sp, o);
                vp += __shfl_xor_sync(0xffffffffu, vp, o);
            }
            // leader lane of each 16-lane row group handles the scalar work
            if (valid && grp == 0) {
                const int seg = __ldg(ids + row);
                const float ex = __expf(sp);        // |sp| < ~7: safe unshifted
                const float ev = ex * vp;
                if (seg != curSeg) {
                    if (curSeg >= 0) {
                        atomicAdd(&g_se[curSeg],  aSe);
                        atomicAdd(&g_sev[curSeg], aSev);
                    }
                    curSeg = seg; aSe = ex; aSev = ev;
                } else {
                    aSe += ex; aSev += ev;
                }
            }
        }
    }
    if (curSeg >= 0) {
        atomicAdd(&g_se[curSeg],  aSe);
        atomicAdd(&g_sev[curSeg], aSev);
    }
}

// FINAL: r_reflections via sorted-ids gather; r_images + unique_ids.
__global__ __launch_bounds__(THREADS)
void final_kernel(const int* __restrict__ ids,
                  float* __restrict__ out,
                  int Btot, int Nimg) {
    const int i = blockIdx.x * blockDim.x + threadIdx.x;
    const float c = g_c, b0 = g_b0;
    if (i < Btot) {
        const int id = __ldg(ids + i);
        const float se = g_se[id];
        out[i] = (se > 0.f) ? __fdividef(g_sev[id], se) + c : b0;
    } else if (i < Btot + Nimg) {
        const int n = i - Btot;
        const float se = g_se[n];
        out[Btot + n]        = (se > 0.f) ? __fdividef(g_sev[n], se) + c : b0;
        out[Btot + Nimg + n] = (float)n;
    }
}

extern "C" void kernel_launch(void* const* d_in, const int* in_sizes, int n_in,
                              void* d_out, int out_size) {
    const float* emb     = (const float*)d_in[0];
    const int*   ids     = (const int*)  d_in[1];
    const float* w_attn  = (const float*)d_in[2];
    // d_in[3] = b_attn: cancels under softmax shift invariance
    const float* w_value = (const float*)d_in[4];
    const float* b_value = (const float*)d_in[5];
    const float* w_out   = (const float*)d_in[6];
    const float* b_out   = (const float*)d_in[7];
    float* out = (float*)d_out;

    const int Btot = in_sizes[0] / EMB;          // 1048576
    const int Nimg = (out_size - Btot) / 2;      // 4096

    pre_kernel<<<(NSEG + THREADS - 1) / THREADS, THREADS>>>(w_value, b_value, w_out, b_out);
    main_kernel<<<MAIN_GRID, THREADS>>>(emb, ids, w_attn, Btot);
    final_kernel<<<(Btot + Nimg + THREADS - 1) / THREADS, THREADS>>>(ids, out, Btot, Nimg);
}

// round 4
// speedup vs baseline: 1.2703x; 1.2703x over previous
#include <cuda_runtime.h>

#define EMB 64
#define NSEG_MAX 4097
#define THREADS 256

__device__ float g_wvo[EMB];     // w_value @ w_out
__device__ float g_c;            // b_value.w_out + b_out
__device__ float g_b0;           // b_out[0]
__device__ int   g_starts[NSEG_MAX];

// Kernel 1: segment bounds scan (streams sorted ids) + fused-head precompute
// (block 0, threads 0..63 do the 64 dot products in parallel with the scan).
__global__ __launch_bounds__(THREADS)
void bounds_kernel(const int*   __restrict__ ids,
                   const float* __restrict__ w_value,
                   const float* __restrict__ b_value,
                   const float* __restrict__ w_out,
                   const float* __restrict__ b_out,
                   int Btot, int Nimg) {
    const int tid = threadIdx.x;
    const int i   = blockIdx.x * THREADS + tid;

    if (blockIdx.x == 0 && tid < EMB) {
        float s = 0.f;
#pragma unroll
        for (int h = 0; h < EMB; ++h)
            s = fmaf(__ldg(w_value + tid * EMB + h), __ldg(w_out + h), s);
        g_wvo[tid] = s;
        if (tid == 0) {
            float c = 0.f;
            for (int h = 0; h < EMB; ++h) c = fmaf(__ldg(b_value + h), __ldg(w_out + h), c);
            g_c  = c + __ldg(b_out);
            g_b0 = __ldg(b_out);
        }
    }

    if (i < Btot) {
        const int cur = __ldg(ids + i);
        if (i == 0) {
            for (int j = 0; j <= cur; ++j) g_starts[j] = 0;
        } else {
            const int prev = __ldg(ids + i - 1);
            for (int j = prev + 1; j <= cur; ++j) g_starts[j] = i;
        }
        if (i == Btot - 1) {
            for (int j = cur + 1; j <= Nimg; ++j) g_starts[j] = Btot;
        }
    }
}

// Kernel 2: one CTA per segment; 16 threads/row float4 loads, shfl reduce,
// unshifted exp (|score| bounded), then contiguous broadcast of r.
__global__ __launch_bounds__(THREADS, 8)
void pool_kernel(const float* __restrict__ emb,
                 const float* __restrict__ w_attn,
                 float* __restrict__ out,
                 int Btot, int Nimg) {
    const int n   = blockIdx.x;
    const int tid = threadIdx.x;

    __shared__ float s_se[8], s_sev[8];
    __shared__ float s_r;

    const int start = g_starts[n];
    const int end   = g_starts[n + 1];

    const int grp = tid & 15;          // column slice [4*grp, 4*grp+4)
    const int rl  = tid >> 4;          // row slot 0..15
    const float4 wa = reinterpret_cast<const float4*>(w_attn)[grp];
    const float4 wv = reinterpret_cast<const float4*>(g_wvo)[grp];

    float se0 = 0.f, sev0 = 0.f, se1 = 0.f, sev1 = 0.f;
    float se2 = 0.f, sev2 = 0.f, se3 = 0.f, sev3 = 0.f;

    for (int base = start; base < end; base += 64) {
        // ---- load phase: 4 independent LDG.128 issued back-to-back ----
        float4 e[4];
        bool   v[4];
#pragma unroll
        for (int u = 0; u < 4; ++u) {
            const int row = base + u * 16 + rl;
            v[u] = row < end;
            e[u] = make_float4(0.f, 0.f, 0.f, 0.f);
            if (v[u]) e[u] = reinterpret_cast<const float4*>(emb + (size_t)row * EMB)[grp];
        }
        // ---- compute phase ----
#pragma unroll
        for (int u = 0; u < 4; ++u) {
            float sp = e[u].x * wa.x + e[u].y * wa.y + e[u].z * wa.z + e[u].w * wa.w;
            float vp = e[u].x * wv.x + e[u].y * wv.y + e[u].z * wv.z + e[u].w * wv.w;
#pragma unroll
            for (int o = 8; o; o >>= 1) {
                sp += __shfl_xor_sync(0xffffffffu, sp, o);
                vp += __shfl_xor_sync(0xffffffffu, vp, o);
            }
            if (v[u]) {
                const float ex = __expf(sp);   // |sp| bounded (~7): unshifted exp is safe
                if      (u == 0) { se0 += ex; sev0 = fmaf(ex, vp, sev0); }
                else if (u == 1) { se1 += ex; sev1 = fmaf(ex, vp, sev1); }
                else if (u == 2) { se2 += ex; sev2 = fmaf(ex, vp, sev2); }
                else             { se3 += ex; sev3 = fmaf(ex, vp, sev3); }
            }
        }
    }

    float se  = (se0 + se1) + (se2 + se3);
    float sev = (sev0 + sev1) + (sev2 + sev3);
    se  += __shfl_xor_sync(0xffffffffu, se,  16);
    sev += __shfl_xor_sync(0xffffffffu, sev, 16);

    const int wid = tid >> 5;
    if ((tid & 31) == 0) { s_se[wid] = se; s_sev[wid] = sev; }
    __syncthreads();

    if (tid == 0) {
        float SE = 0.f, SEV = 0.f;
#pragma unroll
        for (int w = 0; w < 8; ++w) { SE += s_se[w]; SEV += s_sev[w]; }
        const float r = (end == start) ? g_b0 : (SEV / SE + g_c);
        out[Btot + n]        = r;          // r_images
        out[Btot + Nimg + n] = (float)n;   // unique_ids
        s_r = r;
    }
    __syncthreads();

    const float r = s_r;
    for (int i = start + tid; i < end; i += THREADS) out[i] = r;  // r_reflections
}

extern "C" void kernel_launch(void* const* d_in, const int* in_sizes, int n_in,
                              void* d_out, int out_size) {
    const float* emb     = (const float*)d_in[0];
    const int*   ids     = (const int*)  d_in[1];
    const float* w_attn  = (const float*)d_in[2];
    // d_in[3] = b_attn: cancels under softmax shift invariance
    const float* w_value = (const float*)d_in[4];
    const float* b_value = (const float*)d_in[5];
    const float* w_out   = (const float*)d_in[6];
    const float* b_out   = (const float*)d_in[7];
    float* out = (float*)d_out;

    const int Btot = in_sizes[0] / EMB;          // 1048576
    const int Nimg = (out_size - Btot) / 2;      // 4096

    bounds_kernel<<<(Btot + THREADS - 1) / THREADS, THREADS>>>(
        ids, w_value, b_value, w_out, b_out, Btot, Nimg);
    pool_kernel<<<Nimg, THREADS>>>(emb, w_attn, out, Btot, Nimg);
}

// round 5
// speedup vs baseline: 1.3091x; 1.0305x over previous
#include <cuda_runtime.h>

#define EMB 64
#define NSEG_MAX 4097
#define THREADS 256

__device__ float g_wvo[EMB];     // w_value @ w_out
__device__ float g_c;            // b_value.w_out + b_out
__device__ float g_b0;           // b_out[0]
__device__ int   g_starts[NSEG_MAX];

// Kernel 1: segment-bounds scan over sorted ids + fused-head precompute
// (block 0, threads 0..63, runs concurrently with the 4MB ids stream).
__global__ __launch_bounds__(THREADS)
void bounds_kernel(const int*   __restrict__ ids,
                   const float* __restrict__ w_value,
                   const float* __restrict__ b_value,
                   const float* __restrict__ w_out,
                   const float* __restrict__ b_out,
                   int Btot, int Nimg) {
    const int tid = threadIdx.x;
    const int i   = blockIdx.x * THREADS + tid;

    if (blockIdx.x == 0 && tid < EMB) {
        float s = 0.f;
#pragma unroll
        for (int h = 0; h < EMB; ++h)
            s = fmaf(__ldg(w_value + tid * EMB + h), __ldg(w_out + h), s);
        g_wvo[tid] = s;
        if (tid == 0) {
            float c = 0.f;
            for (int h = 0; h < EMB; ++h) c = fmaf(__ldg(b_value + h), __ldg(w_out + h), c);
            g_c  = c + __ldg(b_out);
            g_b0 = __ldg(b_out);
        }
    }

    if (i < Btot) {
        const int cur = __ldg(ids + i);
        if (i == 0) {
            for (int j = 0; j <= cur; ++j) g_starts[j] = 0;
        } else {
            const int prev = __ldg(ids + i - 1);
            for (int j = prev + 1; j <= cur; ++j) g_starts[j] = i;
        }
        if (i == Btot - 1) {
            for (int j = cur + 1; j <= Nimg; ++j) g_starts[j] = Btot;
        }
    }
}

// Kernel 2: one CTA per segment. 16 threads/row, float4 coalesced loads.
// Only the SCORE partial is reduced per row (4 shfls); exp is replicated on
// all 16 lanes and the VALUE partial is accumulated unreduced per-lane,
// with its cross-lane reduction deferred to once per CTA.
__global__ __launch_bounds__(THREADS, 8)
void pool_kernel(const float* __restrict__ emb,
                 const float* __restrict__ w_attn,
                 float* __restrict__ out,
                 int Btot, int Nimg) {
    const int n   = blockIdx.x;
    const int tid = threadIdx.x;

    __shared__ float s_se[8], s_sev[8];
    __shared__ float s_r;

    const int start = g_starts[n];
    const int end   = g_starts[n + 1];
    const int cnt   = end - start;

    const int grp = tid & 15;          // column slice [4*grp, 4*grp+4)
    const int rl  = tid >> 4;          // row slot 0..15
    const float4 wa = reinterpret_cast<const float4*>(w_attn)[grp];
    const float4 wv = reinterpret_cast<const float4*>(g_wvo)[grp];

    float se0 = 0.f, sev0 = 0.f, se1 = 0.f, sev1 = 0.f;
    float se2 = 0.f, sev2 = 0.f, se3 = 0.f, sev3 = 0.f;

    const int nfull = cnt & ~63;       // rows handled by unpredicated blocks
    const int mid   = start + nfull;

    // ---- main loop: no per-row predication ----
    for (int base = start; base < mid; base += 64) {
        float4 e[4];
#pragma unroll
        for (int u = 0; u < 4; ++u)
            e[u] = reinterpret_cast<const float4*>(emb + (size_t)(base + u * 16 + rl) * EMB)[grp];
#pragma unroll
        for (int u = 0; u < 4; ++u) {
            float sp = e[u].x * wa.x + e[u].y * wa.y + e[u].z * wa.z + e[u].w * wa.w;
            float vp = e[u].x * wv.x + e[u].y * wv.y + e[u].z * wv.z + e[u].w * wv.w;
#pragma unroll
            for (int o = 8; o; o >>= 1) sp += __shfl_xor_sync(0xffffffffu, sp, o);
            const float ex = __expf(sp);                // replicated on all 16 lanes
            if      (u == 0) { se0 += ex; sev0 = fmaf(ex, vp, sev0); }
            else if (u == 1) { se1 += ex; sev1 = fmaf(ex, vp, sev1); }
            else if (u == 2) { se2 += ex; sev2 = fmaf(ex, vp, sev2); }
            else             { se3 += ex; sev3 = fmaf(ex, vp, sev3); }
        }
    }

    // ---- tail block: masked ----
    if (mid < end) {
        float4 e[4];
        bool   v[4];
#pragma unroll
        for (int u = 0; u < 4; ++u) {
            const int row = mid + u * 16 + rl;
            v[u] = row < end;
            e[u] = make_float4(0.f, 0.f, 0.f, 0.f);
            if (v[u]) e[u] = reinterpret_cast<const float4*>(emb + (size_t)row * EMB)[grp];
        }
#pragma unroll
        for (int u = 0; u < 4; ++u) {
            float sp = e[u].x * wa.x + e[u].y * wa.y + e[u].z * wa.z + e[u].w * wa.w;
            float vp = e[u].x * wv.x + e[u].y * wv.y + e[u].z * wv.z + e[u].w * wv.w;
#pragma unroll
            for (int o = 8; o; o >>= 1) sp += __shfl_xor_sync(0xffffffffu, sp, o);
            float ex = v[u] ? __expf(sp) : 0.f;
            if      (u == 0) { se0 += ex; sev0 = fmaf(ex, vp, sev0); }
            else if (u == 1) { se1 += ex; sev1 = fmaf(ex, vp, sev1); }
            else if (u == 2) { se2 += ex; sev2 = fmaf(ex, vp, sev2); }
            else             { se3 += ex; sev3 = fmaf(ex, vp, sev3); }
        }
    }

    // se is replicated within each 16-lane group; sum the two groups.
    float se  = (se0 + se1) + (se2 + se3);
    float sev = (sev0 + sev1) + (sev2 + sev3);
    se += __shfl_xor_sync(0xffffffffu, se, 16);
    // sev: deferred full cross-lane reduction (once per CTA)
#pragma unroll
    for (int o = 16; o; o >>= 1) sev += __shfl_xor_sync(0xffffffffu, sev, o);

    const int wid = tid >> 5;
    if ((tid & 31) == 0) { s_se[wid] = se; s_sev[wid] = sev; }
    __syncthreads();

    if (tid == 0) {
        float SE = 0.f, SEV = 0.f;
#pragma unroll
        for (int w = 0; w < 8; ++w) { SE += s_se[w]; SEV += s_sev[w]; }
        const float r = (cnt == 0) ? g_b0 : (SEV / SE + g_c);
        out[Btot + n]        = r;          // r_images
        out[Btot + Nimg + n] = (float)n;   // unique_ids
        s_r = r;
    }
    __syncthreads();

    const float r = s_r;
    for (int i = start + tid; i < end; i += THREADS) out[i] = r;  // r_reflections
}

extern "C" void kernel_launch(void* const* d_in, const int* in_sizes, int n_in,
                              void* d_out, int out_size) {
    const float* emb     = (const float*)d_in[0];
    const int*   ids     = (const int*)  d_in[1];
    const float* w_attn  = (const float*)d_in[2];
    // d_in[3] = b_attn: cancels under softmax shift invariance
    const float* w_value = (const float*)d_in[4];
    const float* b_value = (const float*)d_in[5];
    const float* w_out   = (const float*)d_in[6];
    const float* b_out   = (const float*)d_in[7];
    float* out = (float*)d_out;

    const int Btot = in_sizes[0] / EMB;          // 1048576
    const int Nimg = (out_size - Btot) / 2;      // 4096

    bounds_kernel<<<(Btot + THREADS - 1) / THREADS, THREADS>>>(
        ids, w_value, b_value, w_out, b_out, Btot, Nimg);
    pool_kernel<<<Nimg, THREADS>>>(emb, w_attn, out, Btot, Nimg);
}